// round 2
// baseline (speedup 1.0000x reference)
#include <cuda_runtime.h>

#define B_  2
#define T_  2048
#define H_  1024
#define NH_ 16
#define HS_ 64
#define M_  (B_*T_)

// Scratch (device globals: allocation-free rule)
__device__ float g_Q [B_*NH_*T_*HS_];
__device__ float g_K [B_*NH_*T_*HS_];
__device__ float g_V [B_*NH_*T_*HS_];
__device__ float g_AO[B_*NH_*T_*HS_];
__device__ float g_zerobias[H_];   // zero-initialized at module load, never written

// ---------------------------------------------------------------------------
// C[m,n] = sum_k A[m,k] * W[n,k] + bias[n]
// IN_MODE  0: A row-major [M,K]         1: A in [B,NH,T,HS] layout (k -> h,d)
// OUT_MODE 0: C row-major [M,N]         1: C in [B,NH,T,HS] layout (n -> h,d)
// Tile: 64x64, BK=16, 256 threads, 4x4 micro-tile.
// ---------------------------------------------------------------------------
template<int IN_MODE, int OUT_MODE>
__global__ void gemm64(const float* __restrict__ A, const float* __restrict__ W,
                       const float* __restrict__ bias, float* __restrict__ C)
{
    __shared__ float As[16][65];
    __shared__ float Ws[16][65];
    const int K = H_, N = H_;
    const int tid = threadIdx.x;
    const int m0 = blockIdx.y * 64, n0 = blockIdx.x * 64;
    const int row = tid >> 2;          // 0..63
    const int kc  = (tid & 3) * 4;     // 0,4,8,12
    const int ty = tid >> 4, tx = tid & 15;
    const int r0 = ty * 4, c0 = tx * 4;
    float acc[4][4] = {};

    for (int kk = 0; kk < K; kk += 16) {
        float4 av;
        if (IN_MODE == 0) {
            av = *(const float4*)(A + (size_t)(m0 + row) * K + kk + kc);
        } else {
            int m = m0 + row;
            int b = m >> 11, t = m & (T_ - 1);
            int k = kk + kc;
            int h = k >> 6, d = k & 63;
            av = *(const float4*)(A + (((size_t)(b * NH_ + h) * T_ + t) << 6) + d);
        }
        As[kc + 0][row] = av.x; As[kc + 1][row] = av.y;
        As[kc + 2][row] = av.z; As[kc + 3][row] = av.w;

        float4 wv = *(const float4*)(W + (size_t)(n0 + row) * K + kk + kc);
        Ws[kc + 0][row] = wv.x; Ws[kc + 1][row] = wv.y;
        Ws[kc + 2][row] = wv.z; Ws[kc + 3][row] = wv.w;
        __syncthreads();

        #pragma unroll
        for (int k = 0; k < 16; k++) {
            float a[4], w[4];
            #pragma unroll
            for (int i = 0; i < 4; i++) a[i] = As[k][r0 + i];
            #pragma unroll
            for (int j = 0; j < 4; j++) w[j] = Ws[k][c0 + j];
            #pragma unroll
            for (int i = 0; i < 4; i++)
                #pragma unroll
                for (int j = 0; j < 4; j++)
                    acc[i][j] += a[i] * w[j];
        }
        __syncthreads();
    }

    #pragma unroll
    for (int i = 0; i < 4; i++) {
        int m = m0 + r0 + i;
        #pragma unroll
        for (int j = 0; j < 4; j++) {
            int n = n0 + c0 + j;
            float v = acc[i][j] + bias[n];
            if (OUT_MODE == 0) {
                C[(size_t)m * N + n] = v;
            } else {
                int b = m >> 11, t = m & (T_ - 1);
                int h = n >> 6, d = n & 63;
                C[(((size_t)(b * NH_ + h) * T_ + t) << 6) + d] = v;
            }
        }
    }
}

// ---------------------------------------------------------------------------
// RoPE over Q and K in [B,NH,T,HS] layout. One thread per (b,h,t,pair).
// rope cache layout: (T, HS/2, 2) -> [t][i][{cos,sin}]
// ---------------------------------------------------------------------------
__global__ void rope_kernel(float* __restrict__ Q, float* __restrict__ K,
                            const float* __restrict__ rope)
{
    int idx = blockIdx.x * blockDim.x + threadIdx.x;
    if (idx >= B_ * NH_ * T_ * 32) return;
    int pr = idx & 31;
    int t  = (idx >> 5) & (T_ - 1);
    float c = rope[((t << 5) + pr) * 2 + 0];
    float s = rope[((t << 5) + pr) * 2 + 1];
    int base = idx * 2;
    float xe = Q[base], xo = Q[base + 1];
    Q[base]     = c * xe - s * xo;
    Q[base + 1] = s * xe + c * xo;
    xe = K[base]; xo = K[base + 1];
    K[base]     = c * xe - s * xo;
    K[base + 1] = s * xe + c * xo;
}

// ---------------------------------------------------------------------------
// Flash-style attention. Block = (64 queries) x (one b,h). 256 threads as
// 16x16, 4x4 micro-tiles for S and O. Online softmax with -1e10 replacement
// (matches reference exactly, including fully-masked uniform rows).
// smem strides of 65 floats to avoid bank conflicts.
// ---------------------------------------------------------------------------
__global__ void attn_kernel(const float* __restrict__ Q, const float* __restrict__ Kt,
                            const float* __restrict__ V, const int* __restrict__ masks,
                            float* __restrict__ O)
{
    extern __shared__ float sm[];
    float (*Qs)[65] = (float(*)[65])(sm);
    float (*Ks)[65] = (float(*)[65])(sm + 1 * 64 * 65);
    float (*Vs)[65] = (float(*)[65])(sm + 2 * 64 * 65);
    float (*Ps)[65] = (float(*)[65])(sm + 3 * 64 * 65);

    const int bh = blockIdx.y;
    const int b  = bh >> 4;
    const int q0 = blockIdx.x * 64;
    const int tid = threadIdx.x;
    const int ty = tid >> 4, tx = tid & 15;
    const int r0 = ty * 4, c0 = tx * 4;

    const float* Qg = Q + ((size_t)bh * T_ + q0) * HS_;
    for (int i = tid; i < 64 * 64; i += 256)
        Qs[i >> 6][i & 63] = Qg[i];

    float m_i[4], l_i[4], acc[4][4] = {};
    #pragma unroll
    for (int i = 0; i < 4; i++) { m_i[i] = -1e30f; l_i[i] = 0.f; }

    const int* mrow = masks + b * T_;

    for (int kt = 0; kt < T_ / 64; kt++) {
        const int k0 = kt * 64;
        __syncthreads();   // protect Ks/Vs/Ps from previous iteration's readers
        const float* Kg = Kt + ((size_t)bh * T_ + k0) * HS_;
        const float* Vg = V  + ((size_t)bh * T_ + k0) * HS_;
        for (int i = tid; i < 64 * 64; i += 256) {
            Ks[i >> 6][i & 63] = Kg[i];
            Vs[i >> 6][i & 63] = Vg[i];
        }
        __syncthreads();

        // S = Q K^T (4x4 micro-tile)
        float sv[4][4] = {};
        #pragma unroll
        for (int d = 0; d < 64; d++) {
            float a[4], kb[4];
            #pragma unroll
            for (int i = 0; i < 4; i++) a[i] = Qs[r0 + i][d];
            #pragma unroll
            for (int j = 0; j < 4; j++) kb[j] = Ks[c0 + j][d];
            #pragma unroll
            for (int i = 0; i < 4; i++)
                #pragma unroll
                for (int j = 0; j < 4; j++)
                    sv[i][j] += a[i] * kb[j];
        }

        // scale + causal/key-mask replacement (exactly -1e10, finite)
        int km[4];
        #pragma unroll
        for (int j = 0; j < 4; j++) km[j] = mrow[k0 + c0 + j];
        #pragma unroll
        for (int i = 0; i < 4; i++) {
            int gq = q0 + r0 + i;
            #pragma unroll
            for (int j = 0; j < 4; j++) {
                int gk = k0 + c0 + j;
                float v = sv[i][j] * 0.125f;
                if (gk > gq || km[j]) v = -1e10f;
                sv[i][j] = v;
            }
        }

        // online softmax (row group = 16 threads = half-warp; xor shuffles stay inside)
        #pragma unroll
        for (int i = 0; i < 4; i++) {
            float rm = fmaxf(fmaxf(sv[i][0], sv[i][1]), fmaxf(sv[i][2], sv[i][3]));
            rm = fmaxf(rm, __shfl_xor_sync(0xffffffffu, rm, 1));
            rm = fmaxf(rm, __shfl_xor_sync(0xffffffffu, rm, 2));
            rm = fmaxf(rm, __shfl_xor_sync(0xffffffffu, rm, 4));
            rm = fmaxf(rm, __shfl_xor_sync(0xffffffffu, rm, 8));
            float mnew = fmaxf(m_i[i], rm);
            float corr = __expf(m_i[i] - mnew);
            float psum = 0.f;
            #pragma unroll
            for (int j = 0; j < 4; j++) {
                float p = __expf(sv[i][j] - mnew);
                sv[i][j] = p;
                psum += p;
            }
            psum += __shfl_xor_sync(0xffffffffu, psum, 1);
            psum += __shfl_xor_sync(0xffffffffu, psum, 2);
            psum += __shfl_xor_sync(0xffffffffu, psum, 4);
            psum += __shfl_xor_sync(0xffffffffu, psum, 8);
            l_i[i] = l_i[i] * corr + psum;
            m_i[i] = mnew;
            #pragma unroll
            for (int j = 0; j < 4; j++) acc[i][j] *= corr;
            #pragma unroll
            for (int j = 0; j < 4; j++) Ps[r0 + i][c0 + j] = sv[i][j];
        }
        __syncthreads();

        // O += P V (4x4 micro-tile)
        #pragma unroll 8
        for (int k = 0; k < 64; k++) {
            float p[4], vv[4];
            #pragma unroll
            for (int i = 0; i < 4; i++) p[i] = Ps[r0 + i][k];
            #pragma unroll
            for (int j = 0; j < 4; j++) vv[j] = Vs[k][c0 + j];
            #pragma unroll
            for (int i = 0; i < 4; i++)
                #pragma unroll
                for (int j = 0; j < 4; j++)
                    acc[i][j] += p[i] * vv[j];
        }
    }

    float* Og = O + ((size_t)bh * T_ + q0) * HS_;
    #pragma unroll
    for (int i = 0; i < 4; i++) {
        float inv = 1.f / l_i[i];
        #pragma unroll
        for (int j = 0; j < 4; j++)
            Og[(r0 + i) * HS_ + c0 + j] = acc[i][j] * inv;
    }
}

// ---------------------------------------------------------------------------
extern "C" void kernel_launch(void* const* d_in, const int* in_sizes, int n_in,
                              void* d_out, int out_size)
{
    const float* x     = (const float*)d_in[0];
    const int*   masks = (const int*)  d_in[1];
    const float* Wq    = (const float*)d_in[2];
    const float* bq    = (const float*)d_in[3];
    const float* Wk    = (const float*)d_in[4];
    const float* bk    = (const float*)d_in[5];
    const float* Wv    = (const float*)d_in[6];
    const float* bv    = (const float*)d_in[7];
    const float* Wo    = (const float*)d_in[8];
    const float* rope  = (const float*)d_in[9];
    float* out = (float*)d_out;

    float *qp, *kp, *vp, *aop, *zb;
    cudaGetSymbolAddress((void**)&qp,  g_Q);
    cudaGetSymbolAddress((void**)&kp,  g_K);
    cudaGetSymbolAddress((void**)&vp,  g_V);
    cudaGetSymbolAddress((void**)&aop, g_AO);
    cudaGetSymbolAddress((void**)&zb,  g_zerobias);

    dim3 ggrid(H_ / 64, M_ / 64);   // (16, 64)
    gemm64<0, 1><<<ggrid, 256>>>(x, Wq, bq, qp);
    gemm64<0, 1><<<ggrid, 256>>>(x, Wk, bk, kp);
    gemm64<0, 1><<<ggrid, 256>>>(x, Wv, bv, vp);

    const int nrope = B_ * NH_ * T_ * 32;
    rope_kernel<<<(nrope + 255) / 256, 256>>>(qp, kp, rope);

    const int attn_smem = 4 * 64 * 65 * 4;   // 66,560 B
    cudaFuncSetAttribute(attn_kernel, cudaFuncAttributeMaxDynamicSharedMemorySize, attn_smem);
    attn_kernel<<<dim3(T_ / 64, B_ * NH_), 256, attn_smem>>>(qp, kp, vp, masks, aop);

    gemm64<1, 0><<<ggrid, 256>>>(aop, Wo, zb, out);
}